// round 1
// baseline (speedup 1.0000x reference)
#include <cuda_runtime.h>
#include <math.h>

#define TOK  8192
#define DDIM 512
#define HDIM 2048
#define NEXP 4

// ---------------- device scratch (alloc-free rule: __device__ globals) ----------------
__device__ int   g_cnt[NEXP];
__device__ int   g_bucket[NEXP * TOK];
__device__ float g_sw[TOK];
__device__ __align__(16) float g_h[(long long)TOK * HDIM];   // 64 MB intermediate, reused

// ---------------- zero per-launch state ----------------
__global__ void zero_kernel() {
    if (threadIdx.x < NEXP) g_cnt[threadIdx.x] = 0;
}

// ---------------- router: gate softmax, top-1 bucket, shared-expert weight ----------------
__global__ void router_kernel(const float* __restrict__ x,
                              const float* __restrict__ gW,
                              const float* __restrict__ gb,
                              const float* __restrict__ shw,
                              float* __restrict__ gate_out) {
    int t = (blockIdx.x * blockDim.x + threadIdx.x) >> 5;
    int lane = threadIdx.x & 31;
    if (t >= TOK) return;
    const float* xr = x + (size_t)t * DDIM;
    float a0 = 0.f, a1 = 0.f, a2 = 0.f, a3 = 0.f;
    for (int j = lane; j < DDIM; j += 32) {
        float v = xr[j];
        float4 w = *(const float4*)(gW + 4 * j);
        a0 = fmaf(v, w.x, a0);
        a1 = fmaf(v, w.y, a1);
        a2 = fmaf(v, w.z, a2);
        a3 = fmaf(v, w.w, a3);
    }
    #pragma unroll
    for (int off = 16; off > 0; off >>= 1) {
        a0 += __shfl_xor_sync(0xffffffffu, a0, off);
        a1 += __shfl_xor_sync(0xffffffffu, a1, off);
        a2 += __shfl_xor_sync(0xffffffffu, a2, off);
        a3 += __shfl_xor_sync(0xffffffffu, a3, off);
    }
    if (lane == 0) {
        float l[4];
        l[0] = a0 + gb[0]; l[1] = a1 + gb[1]; l[2] = a2 + gb[2]; l[3] = a3 + gb[3];
        float m = l[0];
        #pragma unroll
        for (int e = 1; e < 4; e++) m = fmaxf(m, l[e]);
        float ex[4], s = 0.f;
        #pragma unroll
        for (int e = 0; e < 4; e++) { ex[e] = expf(l[e] - m); s += ex[e]; }
        float inv = 1.f / s;
        float best = -1.f; int bi = 0;
        #pragma unroll
        for (int e = 0; e < 4; e++) {
            float g = ex[e] * inv;
            gate_out[4 * t + e] = g;
            if (g > best) { best = g; bi = e; }   // strict > : first-max wins (jnp.argmax)
        }
        float sig = 1.f / (1.f + expf(-shw[0]));
        g_sw[t] = (1.f - best) * sig;
        int pos = atomicAdd(&g_cnt[bi], 1);
        g_bucket[bi * TOK + pos] = t;
    }
}

// ---------------- aux loss: deterministic tree reduction ----------------
__global__ void aux_kernel(const float* __restrict__ gate, float* __restrict__ auxp) {
    __shared__ float4 s[1024];
    int tid = threadIdx.x;
    float4 a = make_float4(0.f, 0.f, 0.f, 0.f);
    for (int t = tid; t < TOK; t += 1024) {      // fixed order per thread -> deterministic
        a.x += gate[4 * t + 0];
        a.y += gate[4 * t + 1];
        a.z += gate[4 * t + 2];
        a.w += gate[4 * t + 3];
    }
    s[tid] = a;
    __syncthreads();
    for (int off = 512; off > 0; off >>= 1) {
        if (tid < off) {
            s[tid].x += s[tid + off].x;
            s[tid].y += s[tid + off].y;
            s[tid].z += s[tid + off].z;
            s[tid].w += s[tid + off].w;
        }
        __syncthreads();
    }
    if (tid == 0) {
        const float invT = 1.f / (float)TOK;
        float gm[4] = { s[0].x * invT, s[0].y * invT, s[0].z * invT, s[0].w * invT };
        float aux = 0.f;
        #pragma unroll
        for (int e = 0; e < NEXP; e++)
            aux += ((float)g_cnt[e] * invT) * gm[e];
        *auxp = aux * (float)NEXP * 0.01f;
    }
}

// ---------------- tiled fp32 GEMM, 128x128x16, 8x8 microtile ----------------
// MODE 0: expert GEMM1  : gather(x) @ W1[e] + b1[e] -> gelu -> g_h[token]
// MODE 1: expert GEMM2  : gather(g_h) @ W2[e] + b2[e] -> out[token]
// MODE 2: shared GEMM1  : x @ sW1 + sb1 -> gelu -> g_h
// MODE 3: shared GEMM2  : out[t] += sw[t] * (g_h @ sW2 + sb2)
template<int MODE>
__global__ __launch_bounds__(256)
void gemm_kernel(const float* __restrict__ A_in,
                 const float* __restrict__ Bw,
                 const float* __restrict__ bias,
                 float* __restrict__ Cout,
                 int K, int N)
{
    __shared__ __align__(16) float As[16][128];
    __shared__ __align__(16) float Bs[16][132];

    int Mtot;
    const int* bucket = nullptr;
    const int e = blockIdx.z;
    if (MODE == 0 || MODE == 1) {
        Mtot = g_cnt[e];
        if ((int)(blockIdx.y * 128) >= Mtot) return;
        bucket = g_bucket + e * TOK;
        Bw   += (size_t)e * (size_t)K * N;
        bias += (size_t)e * N;
    } else {
        Mtot = TOK;
    }
    const float* A = (MODE == 1 || MODE == 3) ? (const float*)g_h : A_in;

    const int tid   = threadIdx.x;
    const int mbase = blockIdx.y * 128;
    const int nbase = blockIdx.x * 128;

    // A loader mapping: 2 float4 per thread, transposed store into As
    int rA[2], kA[2], tA[2];
    bool vA[2];
    #pragma unroll
    for (int it = 0; it < 2; it++) {
        int lin = tid + it * 256;
        rA[it] = lin >> 2;
        kA[it] = (lin & 3) * 4;
        int pos = mbase + rA[it];
        if (MODE == 0 || MODE == 1) {
            vA[it] = (pos < Mtot);
            tA[it] = vA[it] ? bucket[pos] : 0;
        } else {
            vA[it] = true;
            tA[it] = pos;
        }
    }

    float acc[8][8];
    #pragma unroll
    for (int i = 0; i < 8; i++)
        #pragma unroll
        for (int j = 0; j < 8; j++) acc[i][j] = 0.f;

    const int ty = tid >> 4;   // 0..15 : rows ty*8..ty*8+7
    const int tx = tid & 15;   // 0..15 : cols tx*8..tx*8+7

    for (int k0 = 0; k0 < K; k0 += 16) {
        #pragma unroll
        for (int it = 0; it < 2; it++) {
            float4 v = make_float4(0.f, 0.f, 0.f, 0.f);
            if (vA[it]) v = *(const float4*)(A + (size_t)tA[it] * K + k0 + kA[it]);
            As[kA[it] + 0][rA[it]] = v.x;
            As[kA[it] + 1][rA[it]] = v.y;
            As[kA[it] + 2][rA[it]] = v.z;
            As[kA[it] + 3][rA[it]] = v.w;
        }
        #pragma unroll
        for (int it = 0; it < 2; it++) {
            int lin = tid + it * 256;
            int br = lin >> 5;
            int bc = (lin & 31) * 4;
            *(float4*)&Bs[br][bc] =
                *(const float4*)(Bw + (size_t)(k0 + br) * N + nbase + bc);
        }
        __syncthreads();
        #pragma unroll
        for (int kk = 0; kk < 16; kk++) {
            float a[8], b[8];
            *(float4*)&a[0] = *(const float4*)&As[kk][ty * 8];
            *(float4*)&a[4] = *(const float4*)&As[kk][ty * 8 + 4];
            *(float4*)&b[0] = *(const float4*)&Bs[kk][tx * 8];
            *(float4*)&b[4] = *(const float4*)&Bs[kk][tx * 8 + 4];
            #pragma unroll
            for (int i = 0; i < 8; i++)
                #pragma unroll
                for (int j = 0; j < 8; j++)
                    acc[i][j] = fmaf(a[i], b[j], acc[i][j]);
        }
        __syncthreads();
    }

    // epilogue
    float bb[8];
    #pragma unroll
    for (int j = 0; j < 8; j++) bb[j] = bias[nbase + tx * 8 + j];

    #pragma unroll
    for (int i = 0; i < 8; i++) {
        int pos = mbase + ty * 8 + i;
        if ((MODE == 0 || MODE == 1) && pos >= Mtot) continue;
        int t = (MODE == 0 || MODE == 1) ? bucket[pos] : pos;
        float v[8];
        #pragma unroll
        for (int j = 0; j < 8; j++) v[j] = acc[i][j] + bb[j];

        if (MODE == 0 || MODE == 2) {
            // exact gelu: 0.5*x*(1+erf(x/sqrt(2)))
            #pragma unroll
            for (int j = 0; j < 8; j++)
                v[j] = 0.5f * v[j] * (1.f + erff(v[j] * 0.70710678118f));
            float* dst = g_h + (size_t)t * HDIM + nbase + tx * 8;
            *(float4*)dst       = *(float4*)&v[0];
            *(float4*)(dst + 4) = *(float4*)&v[4];
        } else if (MODE == 1) {
            float* dst = Cout + (size_t)t * DDIM + nbase + tx * 8;
            *(float4*)dst       = *(float4*)&v[0];
            *(float4*)(dst + 4) = *(float4*)&v[4];
        } else {
            float sw = g_sw[t];
            float* dst = Cout + (size_t)t * DDIM + nbase + tx * 8;
            float4 c0 = *(float4*)dst;
            float4 c1 = *(float4*)(dst + 4);
            c0.x = fmaf(sw, v[0], c0.x);
            c0.y = fmaf(sw, v[1], c0.y);
            c0.z = fmaf(sw, v[2], c0.z);
            c0.w = fmaf(sw, v[3], c0.w);
            c1.x = fmaf(sw, v[4], c1.x);
            c1.y = fmaf(sw, v[5], c1.y);
            c1.z = fmaf(sw, v[6], c1.z);
            c1.w = fmaf(sw, v[7], c1.w);
            *(float4*)dst       = c0;
            *(float4*)(dst + 4) = c1;
        }
    }
}

// ---------------- launch ----------------
extern "C" void kernel_launch(void* const* d_in, const int* in_sizes, int n_in,
                              void* d_out, int out_size) {
    const float* x   = (const float*)d_in[0];
    const float* gW  = (const float*)d_in[1];
    const float* gb  = (const float*)d_in[2];
    const float* W1  = (const float*)d_in[3];
    const float* b1  = (const float*)d_in[4];
    const float* W2  = (const float*)d_in[5];
    const float* b2  = (const float*)d_in[6];
    const float* sW1 = (const float*)d_in[7];
    const float* sb1 = (const float*)d_in[8];
    const float* sW2 = (const float*)d_in[9];
    const float* sb2 = (const float*)d_in[10];
    const float* shw = (const float*)d_in[11];

    float* out  = (float*)d_out;                        // [TOK, DDIM]
    float* auxp = out + (size_t)TOK * DDIM;             // scalar
    float* gate = auxp + 1;                             // [TOK, NEXP]

    zero_kernel<<<1, 32>>>();
    router_kernel<<<TOK / 8, 256>>>(x, gW, gb, shw, gate);
    aux_kernel<<<1, 1024>>>(gate, auxp);

    // expert path (sparse dispatch via buckets)
    {
        dim3 g1(HDIM / 128, TOK / 128, NEXP);
        gemm_kernel<0><<<g1, 256>>>(x, W1, b1, nullptr, DDIM, HDIM);
        dim3 g2(DDIM / 128, TOK / 128, NEXP);
        gemm_kernel<1><<<g2, 256>>>(x, W2, b2, out, HDIM, DDIM);
    }
    // shared expert (reuses g_h after expert GEMM2 consumed it; stream-ordered)
    {
        dim3 g1(HDIM / 128, TOK / 128, 1);
        gemm_kernel<2><<<g1, 256>>>(x, sW1, sb1, nullptr, DDIM, HDIM);
        dim3 g2(DDIM / 128, TOK / 128, 1);
        gemm_kernel<3><<<g2, 256>>>(x, sW2, sb2, out, HDIM, DDIM);
    }
}

// round 3
// speedup vs baseline: 2.1743x; 2.1743x over previous
#include <cuda_runtime.h>
#include <cuda_bf16.h>
#include <math.h>
#include <stdint.h>

#define TOK  8192
#define DDIM 512
#define HDIM 2048
#define NEXP 4

// ---------------- device scratch (alloc-free rule) ----------------
__device__ int   g_cnt[NEXP];
__device__ int   g_bucket[NEXP * TOK];
__device__ float g_sw[TOK];

__device__ __nv_bfloat16 g_x_hi[(size_t)TOK * DDIM];
__device__ __nv_bfloat16 g_x_lo[(size_t)TOK * DDIM];
__device__ __nv_bfloat16 g_h_hi[(size_t)TOK * HDIM];
__device__ __nv_bfloat16 g_h_lo[(size_t)TOK * HDIM];
__device__ __nv_bfloat16 g_w1t_hi[(size_t)NEXP * HDIM * DDIM];  // [E][H][D]
__device__ __nv_bfloat16 g_w1t_lo[(size_t)NEXP * HDIM * DDIM];
__device__ __nv_bfloat16 g_w2t_hi[(size_t)NEXP * DDIM * HDIM];  // [E][D][H]
__device__ __nv_bfloat16 g_w2t_lo[(size_t)NEXP * DDIM * HDIM];
__device__ __nv_bfloat16 g_s1t_hi[(size_t)HDIM * DDIM];         // [H][D]
__device__ __nv_bfloat16 g_s1t_lo[(size_t)HDIM * DDIM];
__device__ __nv_bfloat16 g_s2t_hi[(size_t)DDIM * HDIM];         // [D][H]
__device__ __nv_bfloat16 g_s2t_lo[(size_t)DDIM * HDIM];

// ---------------- helpers ----------------
__device__ __forceinline__ uint32_t smem_u32(const void* p) {
    uint32_t a;
    asm("{ .reg .u64 t; cvta.to.shared.u64 t, %1; cvt.u32.u64 %0, t; }" : "=r"(a) : "l"(p));
    return a;
}
__device__ __forceinline__ void cp16(uint32_t dst, const void* src, bool valid) {
    int sz = valid ? 16 : 0;
    asm volatile("cp.async.cg.shared.global [%0], [%1], 16, %2;\n" :: "r"(dst), "l"(src), "r"(sz));
}
#define CP_COMMIT() asm volatile("cp.async.commit_group;\n" ::: "memory")
#define CP_WAIT2()  asm volatile("cp.async.wait_group 2;\n" ::: "memory")

__device__ __forceinline__ void ldsm4(uint32_t& r0, uint32_t& r1, uint32_t& r2, uint32_t& r3,
                                      uint32_t a) {
    asm volatile("ldmatrix.sync.aligned.m8n8.x4.shared.b16 {%0,%1,%2,%3}, [%4];"
        : "=r"(r0), "=r"(r1), "=r"(r2), "=r"(r3) : "r"(a));
}
__device__ __forceinline__ void mma16816(float* c, const uint32_t* a, const uint32_t* b) {
    asm volatile("mma.sync.aligned.m16n8k16.row.col.f32.bf16.bf16.f32 "
        "{%0,%1,%2,%3}, {%4,%5,%6,%7}, {%8,%9}, {%0,%1,%2,%3};"
        : "+f"(c[0]), "+f"(c[1]), "+f"(c[2]), "+f"(c[3])
        : "r"(a[0]), "r"(a[1]), "r"(a[2]), "r"(a[3]), "r"(b[0]), "r"(b[1]));
}

// ---------------- zero per-launch state ----------------
__global__ void zero_kernel() {
    if (threadIdx.x < NEXP) g_cnt[threadIdx.x] = 0;
}

// ---------------- router ----------------
__global__ void router_kernel(const float* __restrict__ x,
                              const float* __restrict__ gW,
                              const float* __restrict__ gb,
                              const float* __restrict__ shw,
                              float* __restrict__ gate_out) {
    int t = (blockIdx.x * blockDim.x + threadIdx.x) >> 5;
    int lane = threadIdx.x & 31;
    if (t >= TOK) return;
    const float* xr = x + (size_t)t * DDIM;
    float a0 = 0.f, a1 = 0.f, a2 = 0.f, a3 = 0.f;
    for (int j = lane; j < DDIM; j += 32) {
        float v = xr[j];
        float4 w = *(const float4*)(gW + 4 * j);
        a0 = fmaf(v, w.x, a0); a1 = fmaf(v, w.y, a1);
        a2 = fmaf(v, w.z, a2); a3 = fmaf(v, w.w, a3);
    }
    #pragma unroll
    for (int off = 16; off > 0; off >>= 1) {
        a0 += __shfl_xor_sync(0xffffffffu, a0, off);
        a1 += __shfl_xor_sync(0xffffffffu, a1, off);
        a2 += __shfl_xor_sync(0xffffffffu, a2, off);
        a3 += __shfl_xor_sync(0xffffffffu, a3, off);
    }
    if (lane == 0) {
        float l[4] = {a0 + gb[0], a1 + gb[1], a2 + gb[2], a3 + gb[3]};
        float m = fmaxf(fmaxf(l[0], l[1]), fmaxf(l[2], l[3]));
        float ex[4], s = 0.f;
        #pragma unroll
        for (int e = 0; e < 4; e++) { ex[e] = expf(l[e] - m); s += ex[e]; }
        float inv = 1.f / s;
        float best = -1.f; int bi = 0;
        #pragma unroll
        for (int e = 0; e < 4; e++) {
            float g = ex[e] * inv;
            gate_out[4 * t + e] = g;
            if (g > best) { best = g; bi = e; }
        }
        float sig = 1.f / (1.f + expf(-shw[0]));
        g_sw[t] = (1.f - best) * sig;
        int pos = atomicAdd(&g_cnt[bi], 1);
        g_bucket[bi * TOK + pos] = t;
    }
}

// ---------------- aux loss ----------------
__global__ void aux_kernel(const float* __restrict__ gate, float* __restrict__ auxp) {
    __shared__ float4 s[1024];
    int tid = threadIdx.x;
    float4 a = make_float4(0.f, 0.f, 0.f, 0.f);
    for (int t = tid; t < TOK; t += 1024) {
        a.x += gate[4 * t + 0]; a.y += gate[4 * t + 1];
        a.z += gate[4 * t + 2]; a.w += gate[4 * t + 3];
    }
    s[tid] = a;
    __syncthreads();
    for (int off = 512; off > 0; off >>= 1) {
        if (tid < off) {
            s[tid].x += s[tid + off].x; s[tid].y += s[tid + off].y;
            s[tid].z += s[tid + off].z; s[tid].w += s[tid + off].w;
        }
        __syncthreads();
    }
    if (tid == 0) {
        const float invT = 1.f / (float)TOK;
        float gm[4] = { s[0].x * invT, s[0].y * invT, s[0].z * invT, s[0].w * invT };
        float aux = 0.f;
        #pragma unroll
        for (int e = 0; e < NEXP; e++) aux += ((float)g_cnt[e] * invT) * gm[e];
        *auxp = aux * (float)NEXP * 0.01f;
    }
}

// ---------------- fp32 -> bf16 hi/lo split (x) ----------------
__global__ void split_x_kernel(const float* __restrict__ in,
                               __nv_bfloat16* __restrict__ oh,
                               __nv_bfloat16* __restrict__ ol, int n) {
    int i = blockIdx.x * blockDim.x + threadIdx.x;
    if (i >= n) return;
    float v = in[i];
    __nv_bfloat16 h = __float2bfloat16(v);
    oh[i] = h;
    ol[i] = __float2bfloat16(v - __bfloat162float(h));
}

// ---------------- transpose + split: in[R][C] -> out[C][R] hi/lo ----------------
__global__ void transpose_split_kernel(const float* __restrict__ in,
                                       __nv_bfloat16* __restrict__ oh,
                                       __nv_bfloat16* __restrict__ ol,
                                       int R, int C) {
    __shared__ float t[32][33];
    size_t mat = (size_t)R * C;
    in += (size_t)blockIdx.z * mat;
    oh += (size_t)blockIdx.z * mat;
    ol += (size_t)blockIdx.z * mat;
    int cb = blockIdx.x * 32, rb = blockIdx.y * 32;
    int tx = threadIdx.x, ty = threadIdx.y;     // 32 x 8
    #pragma unroll
    for (int i = 0; i < 32; i += 8)
        t[ty + i][tx] = in[(size_t)(rb + ty + i) * C + cb + tx];
    __syncthreads();
    #pragma unroll
    for (int i = 0; i < 32; i += 8) {
        float v = t[tx][ty + i];
        __nv_bfloat16 h = __float2bfloat16(v);
        size_t o = (size_t)(cb + ty + i) * R + rb + tx;
        oh[o] = h;
        ol[o] = __float2bfloat16(v - __bfloat162float(h));
    }
}

// ---------------- split-bf16 mma.sync GEMM ----------------
// CTA 128x128, 256 thr (8 warps 2x4), warp tile 64x32, K-tile 32, 4-stage cp.async.
// smem per stage: 4 tiles (Ah, Al, Bh, Bl), each 128 rows x 40 bf16 (80B stride).
// MODE 0: expert GEMM1 gather(x)@W1[e] -> gelu -> split g_h
// MODE 1: expert GEMM2 gather(g_h)@W2[e] -> out
// MODE 2: shared GEMM1 x@sW1 -> gelu -> split g_h
// MODE 3: shared GEMM2 g_h@sW2 -> out += sw*(.)
#define TILE_B   10240          // 128 * 80
#define STAGE_B  (4 * TILE_B)   // 40960
#define NSTAGE   4
#define SMEM_GEMM (NSTAGE * STAGE_B)

template<int MODE>
__global__ __launch_bounds__(256, 1)
void mma_gemm(const __nv_bfloat16* __restrict__ Ahi_g,
              const __nv_bfloat16* __restrict__ Alo_g,
              const __nv_bfloat16* __restrict__ Bhi_g,
              const __nv_bfloat16* __restrict__ Blo_g,
              const float* __restrict__ bias,
              float* __restrict__ outp,
              int K, int N)
{
    extern __shared__ __align__(16) char smem[];
    const int e = blockIdx.z;
    int Mtot = TOK;
    const int* bucket = nullptr;
    if (MODE == 0 || MODE == 1) {
        Mtot = g_cnt[e];
        if ((int)(blockIdx.y * 128) >= Mtot) return;
        bucket = g_bucket + e * TOK;
        size_t wsz = (size_t)K * N;
        Bhi_g += (size_t)e * wsz; Blo_g += (size_t)e * wsz;
        bias  += (size_t)e * N;
    }
    const int tid = threadIdx.x;
    const int wid = tid >> 5, lane = tid & 31;
    const int mbase = blockIdx.y * 128, nbase = blockIdx.x * 128;
    const uint32_t sb = smem_u32(smem);

    // ---- loader mapping: rows rA0 (0..63), rA1 (64..127), chunk ck (16B) ----
    const int rA0 = tid >> 2, rA1 = 64 + (tid >> 2);
    const int ck  = tid & 3;
    int tok0, tok1; bool v0, v1;
    if (MODE == 0 || MODE == 1) {
        v0 = (mbase + rA0) < Mtot; tok0 = v0 ? bucket[mbase + rA0] : 0;
        v1 = (mbase + rA1) < Mtot; tok1 = v1 ? bucket[mbase + rA1] : 0;
    } else {
        v0 = v1 = true; tok0 = mbase + rA0; tok1 = mbase + rA1;
    }
    const __nv_bfloat16* aH0 = Ahi_g + (size_t)tok0 * K + ck * 8;
    const __nv_bfloat16* aH1 = Ahi_g + (size_t)tok1 * K + ck * 8;
    const __nv_bfloat16* aL0 = Alo_g + (size_t)tok0 * K + ck * 8;
    const __nv_bfloat16* aL1 = Alo_g + (size_t)tok1 * K + ck * 8;
    const __nv_bfloat16* bH0 = Bhi_g + (size_t)(nbase + rA0) * K + ck * 8;
    const __nv_bfloat16* bH1 = Bhi_g + (size_t)(nbase + rA1) * K + ck * 8;
    const __nv_bfloat16* bL0 = Blo_g + (size_t)(nbase + rA0) * K + ck * 8;
    const __nv_bfloat16* bL1 = Blo_g + (size_t)(nbase + rA1) * K + ck * 8;
    const uint32_t oA0 = (uint32_t)rA0 * 80 + ck * 16;
    const uint32_t oA1 = (uint32_t)rA1 * 80 + ck * 16;

    #define LOAD_STAGE(stg, koff) do {                                   \
        uint32_t b_ = sb + (uint32_t)(stg) * STAGE_B;                    \
        cp16(b_ + oA0,              aH0 + (koff), v0);                   \
        cp16(b_ + oA1,              aH1 + (koff), v1);                   \
        cp16(b_ + TILE_B + oA0,     aL0 + (koff), v0);                   \
        cp16(b_ + TILE_B + oA1,     aL1 + (koff), v1);                   \
        cp16(b_ + 2 * TILE_B + oA0, bH0 + (koff), true);                 \
        cp16(b_ + 2 * TILE_B + oA1, bH1 + (koff), true);                 \
        cp16(b_ + 3 * TILE_B + oA0, bL0 + (koff), true);                 \
        cp16(b_ + 3 * TILE_B + oA1, bL1 + (koff), true);                 \
    } while (0)

    const int KT = K / 32;
    LOAD_STAGE(0, 0);  CP_COMMIT();
    LOAD_STAGE(1, 32); CP_COMMIT();
    LOAD_STAGE(2, 64); CP_COMMIT();

    // ---- compute mapping ----
    const int warpM = (wid & 1) * 64;
    const int warpN = (wid >> 1) * 32;
    float acc[4][4][4];
    #pragma unroll
    for (int mi = 0; mi < 4; mi++)
        #pragma unroll
        for (int ni = 0; ni < 4; ni++)
            #pragma unroll
            for (int q = 0; q < 4; q++) acc[mi][ni][q] = 0.f;

    const uint32_t aRowOff = (uint32_t)(warpM + (lane & 15)) * 80 + (lane >> 4) * 16;
    const uint32_t bRowOff = (uint32_t)(warpN + (lane & 7) + ((lane >> 4) << 3)) * 80
                             + ((lane >> 3) & 1) * 16;

    for (int kt = 0; kt < KT; kt++) {
        CP_WAIT2();
        __syncthreads();
        if (kt + 3 < KT) LOAD_STAGE((kt + 3) & 3, (kt + 3) * 32);
        CP_COMMIT();

        uint32_t base = sb + (uint32_t)(kt & 3) * STAGE_B;
        #pragma unroll
        for (int ks = 0; ks < 2; ks++) {
            uint32_t aH[4][4], aL[4][4], bH[4][2], bL[4][2];
            #pragma unroll
            for (int mi = 0; mi < 4; mi++) {
                uint32_t ad = base + aRowOff + (uint32_t)mi * (16 * 80) + ks * 32;
                ldsm4(aH[mi][0], aH[mi][1], aH[mi][2], aH[mi][3], ad);
                ldsm4(aL[mi][0], aL[mi][1], aL[mi][2], aL[mi][3], ad + TILE_B);
            }
            #pragma unroll
            for (int p = 0; p < 2; p++) {
                uint32_t bd = base + 2 * TILE_B + bRowOff + (uint32_t)p * (16 * 80) + ks * 32;
                ldsm4(bH[2*p][0], bH[2*p][1], bH[2*p+1][0], bH[2*p+1][1], bd);
                ldsm4(bL[2*p][0], bL[2*p][1], bL[2*p+1][0], bL[2*p+1][1], bd + TILE_B);
            }
            #pragma unroll
            for (int mi = 0; mi < 4; mi++)
                #pragma unroll
                for (int ni = 0; ni < 4; ni++) {
                    mma16816(acc[mi][ni], aH[mi], bH[ni]);
                    mma16816(acc[mi][ni], aH[mi], bL[ni]);
                    mma16816(acc[mi][ni], aL[mi], bH[ni]);
                }
        }
    }

    // ---- epilogue ----
    float bb[4][2];
    #pragma unroll
    for (int ni = 0; ni < 4; ni++) {
        int n = nbase + warpN + ni * 8 + (lane & 3) * 2;
        bb[ni][0] = bias[n]; bb[ni][1] = bias[n + 1];
    }

    #pragma unroll
    for (int mi = 0; mi < 4; mi++) {
        #pragma unroll
        for (int h = 0; h < 2; h++) {
            int mrow = warpM + mi * 16 + (lane >> 2) + h * 8;
            int pos = mbase + mrow;
            int et; bool ev;
            if (MODE == 0 || MODE == 1) { ev = pos < Mtot; et = ev ? bucket[pos] : 0; }
            else { ev = true; et = pos; }
            if (!ev) continue;
            float swv = (MODE == 3) ? g_sw[et] : 0.f;
            #pragma unroll
            for (int ni = 0; ni < 4; ni++) {
                int n = nbase + warpN + ni * 8 + (lane & 3) * 2;
                float u0 = acc[mi][ni][2 * h]     + bb[ni][0];
                float u1 = acc[mi][ni][2 * h + 1] + bb[ni][1];
                if (MODE == 0 || MODE == 2) {
                    u0 = 0.5f * u0 * (1.f + erff(u0 * 0.70710678118f));
                    u1 = 0.5f * u1 * (1.f + erff(u1 * 0.70710678118f));
                    __nv_bfloat16 h0 = __float2bfloat16(u0);
                    __nv_bfloat16 h1 = __float2bfloat16(u1);
                    __nv_bfloat16 l0 = __float2bfloat16(u0 - __bfloat162float(h0));
                    __nv_bfloat16 l1 = __float2bfloat16(u1 - __bfloat162float(h1));
                    *(__nv_bfloat162*)(g_h_hi + (size_t)et * HDIM + n) =
                        __nv_bfloat162(h0, h1);
                    *(__nv_bfloat162*)(g_h_lo + (size_t)et * HDIM + n) =
                        __nv_bfloat162(l0, l1);
                } else if (MODE == 1) {
                    float2* dst = (float2*)(outp + (size_t)et * DDIM + n);
                    *dst = make_float2(u0, u1);
                } else {
                    float2* dst = (float2*)(outp + (size_t)et * DDIM + n);
                    float2 c = *dst;
                    c.x = fmaf(swv, u0, c.x);
                    c.y = fmaf(swv, u1, c.y);
                    *dst = c;
                }
            }
        }
    }
    #undef LOAD_STAGE
}

// ---------------- launch ----------------
extern "C" void kernel_launch(void* const* d_in, const int* in_sizes, int n_in,
                              void* d_out, int out_size) {
    const float* x   = (const float*)d_in[0];
    const float* gW  = (const float*)d_in[1];
    const float* gb  = (const float*)d_in[2];
    const float* W1  = (const float*)d_in[3];
    const float* b1  = (const float*)d_in[4];
    const float* W2  = (const float*)d_in[5];
    const float* b2  = (const float*)d_in[6];
    const float* sW1 = (const float*)d_in[7];
    const float* sb1 = (const float*)d_in[8];
    const float* sW2 = (const float*)d_in[9];
    const float* sb2 = (const float*)d_in[10];
    const float* shw = (const float*)d_in[11];

    float* out  = (float*)d_out;
    float* auxp = out + (size_t)TOK * DDIM;
    float* gate = auxp + 1;

    cudaFuncSetAttribute(mma_gemm<0>, cudaFuncAttributeMaxDynamicSharedMemorySize, SMEM_GEMM);
    cudaFuncSetAttribute(mma_gemm<1>, cudaFuncAttributeMaxDynamicSharedMemorySize, SMEM_GEMM);
    cudaFuncSetAttribute(mma_gemm<2>, cudaFuncAttributeMaxDynamicSharedMemorySize, SMEM_GEMM);
    cudaFuncSetAttribute(mma_gemm<3>, cudaFuncAttributeMaxDynamicSharedMemorySize, SMEM_GEMM);

    __nv_bfloat16 *xh, *xl, *w1h, *w1l, *w2h, *w2l, *s1h, *s1l, *s2h, *s2l, *hh, *hl;
    cudaGetSymbolAddress((void**)&xh,  g_x_hi);   cudaGetSymbolAddress((void**)&xl,  g_x_lo);
    cudaGetSymbolAddress((void**)&w1h, g_w1t_hi); cudaGetSymbolAddress((void**)&w1l, g_w1t_lo);
    cudaGetSymbolAddress((void**)&w2h, g_w2t_hi); cudaGetSymbolAddress((void**)&w2l, g_w2t_lo);
    cudaGetSymbolAddress((void**)&s1h, g_s1t_hi); cudaGetSymbolAddress((void**)&s1l, g_s1t_lo);
    cudaGetSymbolAddress((void**)&s2h, g_s2t_hi); cudaGetSymbolAddress((void**)&s2l, g_s2t_lo);
    cudaGetSymbolAddress((void**)&hh,  g_h_hi);   cudaGetSymbolAddress((void**)&hl,  g_h_lo);

    zero_kernel<<<1, 32>>>();
    router_kernel<<<TOK / 8, 256>>>(x, gW, gb, shw, gate);
    aux_kernel<<<1, 1024>>>(gate, auxp);

    {
        int n = TOK * DDIM;
        split_x_kernel<<<(n + 255) / 256, 256>>>(x, xh, xl, n);
        dim3 b(32, 8);
        transpose_split_kernel<<<dim3(HDIM / 32, DDIM / 32, NEXP), b>>>(W1, w1h, w1l, DDIM, HDIM);
        transpose_split_kernel<<<dim3(DDIM / 32, HDIM / 32, NEXP), b>>>(W2, w2h, w2l, HDIM, DDIM);
        transpose_split_kernel<<<dim3(HDIM / 32, DDIM / 32, 1),    b>>>(sW1, s1h, s1l, DDIM, HDIM);
        transpose_split_kernel<<<dim3(DDIM / 32, HDIM / 32, 1),    b>>>(sW2, s2h, s2l, HDIM, DDIM);
    }

    // expert path
    mma_gemm<0><<<dim3(HDIM / 128, TOK / 128, NEXP), 256, SMEM_GEMM>>>(
        xh, xl, w1h, w1l, b1, nullptr, DDIM, HDIM);
    mma_gemm<1><<<dim3(DDIM / 128, TOK / 128, NEXP), 256, SMEM_GEMM>>>(
        hh, hl, w2h, w2l, b2, out, HDIM, DDIM);
    // shared expert
    mma_gemm<2><<<dim3(HDIM / 128, TOK / 128, 1), 256, SMEM_GEMM>>>(
        xh, xl, s1h, s1l, sb1, nullptr, DDIM, HDIM);
    mma_gemm<3><<<dim3(DDIM / 128, TOK / 128, 1), 256, SMEM_GEMM>>>(
        hh, hl, s2h, s2l, sb2, out, HDIM, DDIM);
}

// round 4
// speedup vs baseline: 3.3029x; 1.5191x over previous
#include <cuda_runtime.h>
#include <cuda_fp16.h>
#include <math.h>
#include <stdint.h>

#define TOK  8192
#define DDIM 512
#define HDIM 2048
#define NEXP 4

// ---------------- device scratch ----------------
__device__ int   g_cnt[NEXP];
__device__ int   g_bucket[NEXP * TOK];
__device__ float g_sw[TOK];

__device__ __half g_x_hi[(size_t)TOK * DDIM];
__device__ __half g_x_lo[(size_t)TOK * DDIM];
__device__ __half g_h_hi[(size_t)TOK * HDIM];
__device__ __half g_h_lo[(size_t)TOK * HDIM];
__device__ __half g_w1[(size_t)NEXP * DDIM * HDIM];   // [E][D][H] = [E][K][N]
__device__ __half g_w2[(size_t)NEXP * HDIM * DDIM];   // [E][H][D]
__device__ __half g_s1[(size_t)DDIM * HDIM];          // [D][H]
__device__ __half g_s2[(size_t)HDIM * DDIM];          // [H][D]

// ---------------- helpers ----------------
__device__ __forceinline__ uint32_t smem_u32(const void* p) {
    uint32_t a;
    asm("{ .reg .u64 t; cvta.to.shared.u64 t, %1; cvt.u32.u64 %0, t; }" : "=r"(a) : "l"(p));
    return a;
}
__device__ __forceinline__ void cp16(uint32_t dst, const void* src, bool valid) {
    int sz = valid ? 16 : 0;
    asm volatile("cp.async.cg.shared.global [%0], [%1], 16, %2;\n" :: "r"(dst), "l"(src), "r"(sz));
}
#define CP_COMMIT() asm volatile("cp.async.commit_group;\n" ::: "memory")
#define CP_WAIT1()  asm volatile("cp.async.wait_group 1;\n" ::: "memory")

__device__ __forceinline__ void ldsm4(uint32_t& r0, uint32_t& r1, uint32_t& r2, uint32_t& r3,
                                      uint32_t a) {
    asm volatile("ldmatrix.sync.aligned.m8n8.x4.shared.b16 {%0,%1,%2,%3}, [%4];"
        : "=r"(r0), "=r"(r1), "=r"(r2), "=r"(r3) : "r"(a));
}
__device__ __forceinline__ void ldsm4t(uint32_t& r0, uint32_t& r1, uint32_t& r2, uint32_t& r3,
                                       uint32_t a) {
    asm volatile("ldmatrix.sync.aligned.m8n8.x4.trans.shared.b16 {%0,%1,%2,%3}, [%4];"
        : "=r"(r0), "=r"(r1), "=r"(r2), "=r"(r3) : "r"(a));
}
__device__ __forceinline__ void mma16816(float* c, const uint32_t* a, const uint32_t* b) {
    asm volatile("mma.sync.aligned.m16n8k16.row.col.f32.f16.f16.f32 "
        "{%0,%1,%2,%3}, {%4,%5,%6,%7}, {%8,%9}, {%0,%1,%2,%3};"
        : "+f"(c[0]), "+f"(c[1]), "+f"(c[2]), "+f"(c[3])
        : "r"(a[0]), "r"(a[1]), "r"(a[2]), "r"(a[3]), "r"(b[0]), "r"(b[1]));
}

// ---------------- zero per-launch state ----------------
__global__ void zero_kernel() {
    if (threadIdx.x < NEXP) g_cnt[threadIdx.x] = 0;
}

// ---------------- router ----------------
__global__ void router_kernel(const float* __restrict__ x,
                              const float* __restrict__ gW,
                              const float* __restrict__ gb,
                              const float* __restrict__ shw,
                              float* __restrict__ gate_out) {
    int t = (blockIdx.x * blockDim.x + threadIdx.x) >> 5;
    int lane = threadIdx.x & 31;
    if (t >= TOK) return;
    const float* xr = x + (size_t)t * DDIM;
    float a0 = 0.f, a1 = 0.f, a2 = 0.f, a3 = 0.f;
    for (int j = lane; j < DDIM; j += 32) {
        float v = xr[j];
        float4 w = *(const float4*)(gW + 4 * j);
        a0 = fmaf(v, w.x, a0); a1 = fmaf(v, w.y, a1);
        a2 = fmaf(v, w.z, a2); a3 = fmaf(v, w.w, a3);
    }
    #pragma unroll
    for (int off = 16; off > 0; off >>= 1) {
        a0 += __shfl_xor_sync(0xffffffffu, a0, off);
        a1 += __shfl_xor_sync(0xffffffffu, a1, off);
        a2 += __shfl_xor_sync(0xffffffffu, a2, off);
        a3 += __shfl_xor_sync(0xffffffffu, a3, off);
    }
    if (lane == 0) {
        float l[4] = {a0 + gb[0], a1 + gb[1], a2 + gb[2], a3 + gb[3]};
        float m = fmaxf(fmaxf(l[0], l[1]), fmaxf(l[2], l[3]));
        float ex[4], s = 0.f;
        #pragma unroll
        for (int e = 0; e < 4; e++) { ex[e] = expf(l[e] - m); s += ex[e]; }
        float inv = 1.f / s;
        float best = -1.f; int bi = 0;
        #pragma unroll
        for (int e = 0; e < 4; e++) {
            float g = ex[e] * inv;
            gate_out[4 * t + e] = g;
            if (g > best) { best = g; bi = e; }
        }
        float sig = 1.f / (1.f + expf(-shw[0]));
        g_sw[t] = (1.f - best) * sig;
        int pos = atomicAdd(&g_cnt[bi], 1);
        g_bucket[bi * TOK + pos] = t;
    }
}

// ---------------- aux loss ----------------
__global__ void aux_kernel(const float* __restrict__ gate, float* __restrict__ auxp) {
    __shared__ float4 s[1024];
    int tid = threadIdx.x;
    float4 a = make_float4(0.f, 0.f, 0.f, 0.f);
    for (int t = tid; t < TOK; t += 1024) {
        a.x += gate[4 * t + 0]; a.y += gate[4 * t + 1];
        a.z += gate[4 * t + 2]; a.w += gate[4 * t + 3];
    }
    s[tid] = a;
    __syncthreads();
    for (int off = 512; off > 0; off >>= 1) {
        if (tid < off) {
            s[tid].x += s[tid + off].x; s[tid].y += s[tid + off].y;
            s[tid].z += s[tid + off].z; s[tid].w += s[tid + off].w;
        }
        __syncthreads();
    }
    if (tid == 0) {
        const float invT = 1.f / (float)TOK;
        float gm[4] = { s[0].x * invT, s[0].y * invT, s[0].z * invT, s[0].w * invT };
        float aux = 0.f;
        #pragma unroll
        for (int e = 0; e < NEXP; e++) aux += ((float)g_cnt[e] * invT) * gm[e];
        *auxp = aux * (float)NEXP * 0.01f;
    }
}

// ---------------- fp32 -> fp16 hi/lo split (x), 4 elems/thread ----------------
__global__ void split_x_kernel(const float* __restrict__ in,
                               __half* __restrict__ oh,
                               __half* __restrict__ ol, int n4) {
    int i = blockIdx.x * blockDim.x + threadIdx.x;
    if (i >= n4) return;
    float4 v = ((const float4*)in)[i];
    __half h0 = __float2half(v.x), h1 = __float2half(v.y);
    __half h2 = __float2half(v.z), h3 = __float2half(v.w);
    ((__half2*)oh)[2 * i]     = __halves2half2(h0, h1);
    ((__half2*)oh)[2 * i + 1] = __halves2half2(h2, h3);
    ((__half2*)ol)[2 * i] = __halves2half2(
        __float2half(v.x - __half2float(h0)), __float2half(v.y - __half2float(h1)));
    ((__half2*)ol)[2 * i + 1] = __halves2half2(
        __float2half(v.z - __half2float(h2)), __float2half(v.w - __half2float(h3)));
}

// ---------------- fp32 -> fp16 convert (weights), 4 elems/thread ----------------
__global__ void convert_kernel(const float* __restrict__ in,
                               __half* __restrict__ out, int n4) {
    int i = blockIdx.x * blockDim.x + threadIdx.x;
    if (i >= n4) return;
    float4 v = ((const float4*)in)[i];
    ((__half2*)out)[2 * i]     = __halves2half2(__float2half(v.x), __float2half(v.y));
    ((__half2*)out)[2 * i + 1] = __halves2half2(__float2half(v.z), __float2half(v.w));
}

// ---------------- split-fp16 mma.sync GEMM ----------------
// CTA 128x128, 8 warps (2x4), warp tile 64x32, K-tile 32, 3-stage cp.async, occ 2.
// A (activations) = hi/lo fp16 row-major [M][K]; B (weights) fp16 row-major [K][N],
// loaded with ldmatrix.trans. 2 mma products: Ah*B + Al*B.
// MODE 0: expert GEMM1 gather(x)@W1[e] -> gelu -> split g_h
// MODE 1: expert GEMM2 gather(g_h)@W2[e] -> out
// MODE 2: shared GEMM1 x@sW1 -> gelu -> split g_h
// MODE 3: shared GEMM2 g_h@sW2 -> out += sw*(.)
#define A_TILE_B 10240           // 128 rows * 80B (64B data + 16 pad)
#define B_TILE_B 8704            // 32 rows * 272B (256B data + 16 pad)
#define B_OFF    (2 * A_TILE_B)  // 20480
#define STAGE_B  (B_OFF + B_TILE_B)  // 29184
#define NSTAGE   3
#define SMEM_GEMM (NSTAGE * STAGE_B) // 87552

template<int MODE>
__global__ __launch_bounds__(256, 2)
void mma_gemm(const __half* __restrict__ Ahi_g,
              const __half* __restrict__ Alo_g,
              const __half* __restrict__ Bg,
              const float* __restrict__ bias,
              float* __restrict__ outp,
              int K, int N)
{
    extern __shared__ __align__(16) char smem[];
    const int e = blockIdx.z;
    int Mtot = TOK;
    const int* bucket = nullptr;
    if (MODE == 0 || MODE == 1) {
        Mtot = g_cnt[e];
        if ((int)(blockIdx.y * 128) >= Mtot) return;
        bucket = g_bucket + e * TOK;
        Bg   += (size_t)e * (size_t)K * N;
        bias += (size_t)e * N;
    }
    const int tid = threadIdx.x;
    const int wid = tid >> 5, lane = tid & 31;
    const int mbase = blockIdx.y * 128, nbase = blockIdx.x * 128;
    const uint32_t sb = smem_u32(smem);

    // ---- A loader: rows rA0 (0..63), rA1 (64..127), 16B chunk ck ----
    const int rA0 = tid >> 2, rA1 = 64 + (tid >> 2);
    const int ck  = tid & 3;
    int tok0, tok1; bool v0, v1;
    if (MODE == 0 || MODE == 1) {
        v0 = (mbase + rA0) < Mtot; tok0 = v0 ? bucket[mbase + rA0] : 0;
        v1 = (mbase + rA1) < Mtot; tok1 = v1 ? bucket[mbase + rA1] : 0;
    } else {
        v0 = v1 = true; tok0 = mbase + rA0; tok1 = mbase + rA1;
    }
    const __half* aH0 = Ahi_g + (size_t)tok0 * K + ck * 8;
    const __half* aH1 = Ahi_g + (size_t)tok1 * K + ck * 8;
    const __half* aL0 = Alo_g + (size_t)tok0 * K + ck * 8;
    const __half* aL1 = Alo_g + (size_t)tok1 * K + ck * 8;
    const uint32_t oA0 = (uint32_t)rA0 * 80 + ck * 16;
    const uint32_t oA1 = (uint32_t)rA1 * 80 + ck * 16;

    // ---- B loader: 32 k-rows x 256B, thread -> row tid>>3, chunks (tid&7), +8 ----
    const int rB = tid >> 3, cB = tid & 7;
    const __half* bp = Bg + (size_t)rB * N + nbase + cB * 8;
    const uint32_t oB = (uint32_t)rB * 272 + cB * 16;

    #define LOAD_STAGE(stg, koff) do {                                       \
        uint32_t b_ = sb + (uint32_t)(stg) * STAGE_B;                        \
        cp16(b_ + oA0,            aH0 + (koff), v0);                         \
        cp16(b_ + oA1,            aH1 + (koff), v1);                         \
        cp16(b_ + A_TILE_B + oA0, aL0 + (koff), v0);                         \
        cp16(b_ + A_TILE_B + oA1, aL1 + (koff), v1);                         \
        cp16(b_ + B_OFF + oB,       bp + (size_t)(koff) * N, true);          \
        cp16(b_ + B_OFF + oB + 128, bp + (size_t)(koff) * N + 64, true);     \
    } while (0)

    const int KT = K / 32;
    LOAD_STAGE(0, 0);  CP_COMMIT();
    LOAD_STAGE(1, 32); CP_COMMIT();

    // ---- compute mapping ----
    const int warpM = (wid & 1) * 64;
    const int warpN = (wid >> 1) * 32;
    float acc[4][4][4];
    #pragma unroll
    for (int mi = 0; mi < 4; mi++)
        #pragma unroll
        for (int ni = 0; ni < 4; ni++)
            #pragma unroll
            for (int q = 0; q < 4; q++) acc[mi][ni][q] = 0.f;

    const uint32_t aRowOff = (uint32_t)(warpM + (lane & 15)) * 80 + (lane >> 4) * 16;
    // B trans addresses: krow = (lane&7) + ((lane>>3)&1)*8, nbyte = (lane>>4)*16
    const uint32_t bOffBase = (uint32_t)((lane & 7) + ((lane >> 3) & 1) * 8) * 272
                              + (uint32_t)warpN * 2 + (uint32_t)(lane >> 4) * 16;

    int s_c = 0;
    for (int kt = 0; kt < KT; kt++) {
        CP_WAIT1();
        __syncthreads();
        if (kt + 2 < KT) {
            int s_l = s_c + 2; if (s_l >= NSTAGE) s_l -= NSTAGE;
            LOAD_STAGE(s_l, (kt + 2) * 32);
        }
        CP_COMMIT();

        uint32_t base = sb + (uint32_t)s_c * STAGE_B;
        #pragma unroll
        for (int ks = 0; ks < 2; ks++) {
            uint32_t bF[4][2];
            #pragma unroll
            for (int p = 0; p < 2; p++) {
                uint32_t r0, r1, r2, r3;
                ldsm4t(r0, r1, r2, r3,
                       base + B_OFF + bOffBase + (uint32_t)ks * (16 * 272) + (uint32_t)p * 32);
                bF[2 * p][0] = r0; bF[2 * p][1] = r1;
                bF[2 * p + 1][0] = r2; bF[2 * p + 1][1] = r3;
            }
            {
                uint32_t aH[4][4];
                #pragma unroll
                for (int mi = 0; mi < 4; mi++) {
                    uint32_t ad = base + aRowOff + (uint32_t)mi * (16 * 80) + ks * 32;
                    ldsm4(aH[mi][0], aH[mi][1], aH[mi][2], aH[mi][3], ad);
                }
                #pragma unroll
                for (int mi = 0; mi < 4; mi++)
                    #pragma unroll
                    for (int ni = 0; ni < 4; ni++)
                        mma16816(acc[mi][ni], aH[mi], bF[ni]);
            }
            {
                uint32_t aL[4][4];
                #pragma unroll
                for (int mi = 0; mi < 4; mi++) {
                    uint32_t ad = base + A_TILE_B + aRowOff + (uint32_t)mi * (16 * 80) + ks * 32;
                    ldsm4(aL[mi][0], aL[mi][1], aL[mi][2], aL[mi][3], ad);
                }
                #pragma unroll
                for (int mi = 0; mi < 4; mi++)
                    #pragma unroll
                    for (int ni = 0; ni < 4; ni++)
                        mma16816(acc[mi][ni], aL[mi], bF[ni]);
            }
        }
        s_c = (s_c + 1 == NSTAGE) ? 0 : s_c + 1;
    }

    // ---- epilogue ----
    float bb[4][2];
    #pragma unroll
    for (int ni = 0; ni < 4; ni++) {
        int n = nbase + warpN + ni * 8 + (lane & 3) * 2;
        bb[ni][0] = bias[n]; bb[ni][1] = bias[n + 1];
    }

    #pragma unroll
    for (int mi = 0; mi < 4; mi++) {
        #pragma unroll
        for (int h = 0; h < 2; h++) {
            int mrow = warpM + mi * 16 + (lane >> 2) + h * 8;
            int pos = mbase + mrow;
            int et; bool ev;
            if (MODE == 0 || MODE == 1) { ev = pos < Mtot; et = ev ? bucket[pos] : 0; }
            else { ev = true; et = pos; }
            if (!ev) continue;
            float swv = (MODE == 3) ? g_sw[et] : 0.f;
            #pragma unroll
            for (int ni = 0; ni < 4; ni++) {
                int n = nbase + warpN + ni * 8 + (lane & 3) * 2;
                float u0 = acc[mi][ni][2 * h]     + bb[ni][0];
                float u1 = acc[mi][ni][2 * h + 1] + bb[ni][1];
                if (MODE == 0 || MODE == 2) {
                    u0 = 0.5f * u0 * (1.f + erff(u0 * 0.70710678118f));
                    u1 = 0.5f * u1 * (1.f + erff(u1 * 0.70710678118f));
                    __half h0 = __float2half(u0);
                    __half h1 = __float2half(u1);
                    __half l0 = __float2half(u0 - __half2float(h0));
                    __half l1 = __float2half(u1 - __half2float(h1));
                    *(__half2*)(g_h_hi + (size_t)et * HDIM + n) = __halves2half2(h0, h1);
                    *(__half2*)(g_h_lo + (size_t)et * HDIM + n) = __halves2half2(l0, l1);
                } else if (MODE == 1) {
                    *(float2*)(outp + (size_t)et * DDIM + n) = make_float2(u0, u1);
                } else {
                    float2* dst = (float2*)(outp + (size_t)et * DDIM + n);
                    float2 c = *dst;
                    c.x = fmaf(swv, u0, c.x);
                    c.y = fmaf(swv, u1, c.y);
                    *dst = c;
                }
            }
        }
    }
    #undef LOAD_STAGE
}

// ---------------- launch ----------------
extern "C" void kernel_launch(void* const* d_in, const int* in_sizes, int n_in,
                              void* d_out, int out_size) {
    const float* x   = (const float*)d_in[0];
    const float* gW  = (const float*)d_in[1];
    const float* gb  = (const float*)d_in[2];
    const float* W1  = (const float*)d_in[3];
    const float* b1  = (const float*)d_in[4];
    const float* W2  = (const float*)d_in[5];
    const float* b2  = (const float*)d_in[6];
    const float* sW1 = (const float*)d_in[7];
    const float* sb1 = (const float*)d_in[8];
    const float* sW2 = (const float*)d_in[9];
    const float* sb2 = (const float*)d_in[10];
    const float* shw = (const float*)d_in[11];

    float* out  = (float*)d_out;
    float* auxp = out + (size_t)TOK * DDIM;
    float* gate = auxp + 1;

    cudaFuncSetAttribute(mma_gemm<0>, cudaFuncAttributeMaxDynamicSharedMemorySize, SMEM_GEMM);
    cudaFuncSetAttribute(mma_gemm<1>, cudaFuncAttributeMaxDynamicSharedMemorySize, SMEM_GEMM);
    cudaFuncSetAttribute(mma_gemm<2>, cudaFuncAttributeMaxDynamicSharedMemorySize, SMEM_GEMM);
    cudaFuncSetAttribute(mma_gemm<3>, cudaFuncAttributeMaxDynamicSharedMemorySize, SMEM_GEMM);

    __half *xh, *xl, *w1, *w2, *s1, *s2, *hh, *hl;
    cudaGetSymbolAddress((void**)&xh, g_x_hi); cudaGetSymbolAddress((void**)&xl, g_x_lo);
    cudaGetSymbolAddress((void**)&w1, g_w1);   cudaGetSymbolAddress((void**)&w2, g_w2);
    cudaGetSymbolAddress((void**)&s1, g_s1);   cudaGetSymbolAddress((void**)&s2, g_s2);
    cudaGetSymbolAddress((void**)&hh, g_h_hi); cudaGetSymbolAddress((void**)&hl, g_h_lo);

    zero_kernel<<<1, 32>>>();
    router_kernel<<<TOK / 8, 256>>>(x, gW, gb, shw, gate);
    aux_kernel<<<1, 1024>>>(gate, auxp);

    {
        int n4 = TOK * DDIM / 4;
        split_x_kernel<<<(n4 + 255) / 256, 256>>>(x, xh, xl, n4);
        int w4 = NEXP * DDIM * HDIM / 4;
        convert_kernel<<<(w4 + 255) / 256, 256>>>(W1, w1, w4);
        convert_kernel<<<(w4 + 255) / 256, 256>>>(W2, w2, w4);
        int sw4 = DDIM * HDIM / 4;
        convert_kernel<<<(sw4 + 255) / 256, 256>>>(sW1, s1, sw4);
        convert_kernel<<<(sw4 + 255) / 256, 256>>>(sW2, s2, sw4);
    }

    // expert path
    mma_gemm<0><<<dim3(HDIM / 128, TOK / 128, NEXP), 256, SMEM_GEMM>>>(
        xh, xl, w1, b1, nullptr, DDIM, HDIM);
    mma_gemm<1><<<dim3(DDIM / 128, TOK / 128, NEXP), 256, SMEM_GEMM>>>(
        hh, hl, w2, b2, out, HDIM, DDIM);
    // shared expert
    mma_gemm<2><<<dim3(HDIM / 128, TOK / 128, 1), 256, SMEM_GEMM>>>(
        xh, xl, s1, sb1, nullptr, DDIM, HDIM);
    mma_gemm<3><<<dim3(DDIM / 128, TOK / 128, 1), 256, SMEM_GEMM>>>(
        hh, hl, s2, sb2, out, HDIM, DDIM);
}

// round 5
// speedup vs baseline: 5.6112x; 1.6989x over previous
#include <cuda_runtime.h>
#include <cuda_fp16.h>
#include <math.h>
#include <stdint.h>

#define TOK  8192
#define DDIM 512
#define HDIM 2048
#define NEXP 4

// ---------------- device scratch ----------------
__device__ int   g_cnt[NEXP];
__device__ int   g_bucket[NEXP * TOK];
__device__ float g_sw[TOK];

__device__ __half g_xf[(size_t)TOK * DDIM];
__device__ __half g_he[(size_t)TOK * HDIM];           // expert-path hidden
__device__ __half g_hs[(size_t)TOK * HDIM];           // shared-path hidden
__device__ __half g_w1[(size_t)NEXP * DDIM * HDIM];   // [E][D][H] (K-major rows)
__device__ __half g_w2[(size_t)NEXP * HDIM * DDIM];   // [E][H][D]
__device__ __half g_s1[(size_t)DDIM * HDIM];          // [D][H]
__device__ __half g_s2[(size_t)HDIM * DDIM];          // [H][D]

// ---------------- helpers ----------------
__device__ __forceinline__ uint32_t smem_u32(const void* p) {
    uint32_t a;
    asm("{ .reg .u64 t; cvta.to.shared.u64 t, %1; cvt.u32.u64 %0, t; }" : "=r"(a) : "l"(p));
    return a;
}
__device__ __forceinline__ void cp16(uint32_t dst, const void* src, bool valid) {
    int sz = valid ? 16 : 0;
    asm volatile("cp.async.cg.shared.global [%0], [%1], 16, %2;\n" :: "r"(dst), "l"(src), "r"(sz));
}
#define CP_COMMIT() asm volatile("cp.async.commit_group;\n" ::: "memory")
#define CP_WAIT2()  asm volatile("cp.async.wait_group 2;\n" ::: "memory")

__device__ __forceinline__ void ldsm4(uint32_t& r0, uint32_t& r1, uint32_t& r2, uint32_t& r3,
                                      uint32_t a) {
    asm volatile("ldmatrix.sync.aligned.m8n8.x4.shared.b16 {%0,%1,%2,%3}, [%4];"
        : "=r"(r0), "=r"(r1), "=r"(r2), "=r"(r3) : "r"(a));
}
__device__ __forceinline__ void ldsm4t(uint32_t& r0, uint32_t& r1, uint32_t& r2, uint32_t& r3,
                                       uint32_t a) {
    asm volatile("ldmatrix.sync.aligned.m8n8.x4.trans.shared.b16 {%0,%1,%2,%3}, [%4];"
        : "=r"(r0), "=r"(r1), "=r"(r2), "=r"(r3) : "r"(a));
}
__device__ __forceinline__ void mma16816(float* c, const uint32_t* a, const uint32_t* b) {
    asm volatile("mma.sync.aligned.m16n8k16.row.col.f32.f16.f16.f32 "
        "{%0,%1,%2,%3}, {%4,%5,%6,%7}, {%8,%9}, {%0,%1,%2,%3};"
        : "+f"(c[0]), "+f"(c[1]), "+f"(c[2]), "+f"(c[3])
        : "r"(a[0]), "r"(a[1]), "r"(a[2]), "r"(a[3]), "r"(b[0]), "r"(b[1]));
}

// ---------------- zero counters ----------------
__global__ void zero_kernel() {
    if (threadIdx.x < NEXP) g_cnt[threadIdx.x] = 0;
}

// ---------------- router ----------------
__global__ void router_kernel(const float* __restrict__ x,
                              const float* __restrict__ gW,
                              const float* __restrict__ gb,
                              const float* __restrict__ shw,
                              float* __restrict__ gate_out) {
    int t = (blockIdx.x * blockDim.x + threadIdx.x) >> 5;
    int lane = threadIdx.x & 31;
    if (t >= TOK) return;
    const float* xr = x + (size_t)t * DDIM;
    float a0 = 0.f, a1 = 0.f, a2 = 0.f, a3 = 0.f;
    for (int j = lane; j < DDIM; j += 32) {
        float v = xr[j];
        float4 w = *(const float4*)(gW + 4 * j);
        a0 = fmaf(v, w.x, a0); a1 = fmaf(v, w.y, a1);
        a2 = fmaf(v, w.z, a2); a3 = fmaf(v, w.w, a3);
    }
    #pragma unroll
    for (int off = 16; off > 0; off >>= 1) {
        a0 += __shfl_xor_sync(0xffffffffu, a0, off);
        a1 += __shfl_xor_sync(0xffffffffu, a1, off);
        a2 += __shfl_xor_sync(0xffffffffu, a2, off);
        a3 += __shfl_xor_sync(0xffffffffu, a3, off);
    }
    if (lane == 0) {
        float l[4] = {a0 + gb[0], a1 + gb[1], a2 + gb[2], a3 + gb[3]};
        float m = fmaxf(fmaxf(l[0], l[1]), fmaxf(l[2], l[3]));
        float ex[4], s = 0.f;
        #pragma unroll
        for (int e = 0; e < 4; e++) { ex[e] = expf(l[e] - m); s += ex[e]; }
        float inv = 1.f / s;
        float best = -1.f; int bi = 0;
        #pragma unroll
        for (int e = 0; e < 4; e++) {
            float g = ex[e] * inv;
            gate_out[4 * t + e] = g;
            if (g > best) { best = g; bi = e; }
        }
        float sig = 1.f / (1.f + expf(-shw[0]));
        g_sw[t] = (1.f - best) * sig;
        int pos = atomicAdd(&g_cnt[bi], 1);
        g_bucket[bi * TOK + pos] = t;
    }
}

// ---------------- aux loss ----------------
__global__ void aux_kernel(const float* __restrict__ gate, float* __restrict__ auxp) {
    __shared__ float4 s[1024];
    int tid = threadIdx.x;
    float4 a = make_float4(0.f, 0.f, 0.f, 0.f);
    for (int t = tid; t < TOK; t += 1024) {
        a.x += gate[4 * t + 0]; a.y += gate[4 * t + 1];
        a.z += gate[4 * t + 2]; a.w += gate[4 * t + 3];
    }
    s[tid] = a;
    __syncthreads();
    for (int off = 512; off > 0; off >>= 1) {
        if (tid < off) {
            s[tid].x += s[tid + off].x; s[tid].y += s[tid + off].y;
            s[tid].z += s[tid + off].z; s[tid].w += s[tid + off].w;
        }
        __syncthreads();
    }
    if (tid == 0) {
        const float invT = 1.f / (float)TOK;
        float gm[4] = { s[0].x * invT, s[0].y * invT, s[0].z * invT, s[0].w * invT };
        float aux = 0.f;
        #pragma unroll
        for (int e = 0; e < NEXP; e++) aux += ((float)g_cnt[e] * invT) * gm[e];
        *auxp = aux * (float)NEXP * 0.01f;
    }
}

// ---------------- fused fp32 -> fp16 convert: x, W1, W2, sW1, sW2 ----------------
#define N4_X  (TOK * DDIM / 4)
#define N4_W  (NEXP * DDIM * HDIM / 4)
#define N4_S  (DDIM * HDIM / 4)
#define N4_TOTAL (N4_X + 2 * N4_W + 2 * N4_S)

__global__ void convert_all_kernel(const float* __restrict__ x,
                                   const float* __restrict__ W1,
                                   const float* __restrict__ W2,
                                   const float* __restrict__ sW1,
                                   const float* __restrict__ sW2,
                                   __half* xf, __half* w1, __half* w2,
                                   __half* s1, __half* s2) {
    int i = blockIdx.x * blockDim.x + threadIdx.x;
    if (i >= N4_TOTAL) return;
    const float* src; __half* dst; int j = i;
    if (j < N4_X) { src = x; dst = xf; }
    else if ((j -= N4_X) < N4_W) { src = W1; dst = w1; }
    else if ((j -= N4_W) < N4_W) { src = W2; dst = w2; }
    else if ((j -= N4_W) < N4_S) { src = sW1; dst = s1; }
    else { j -= N4_S; src = sW2; dst = s2; }
    float4 v = ((const float4*)src)[j];
    ((__half2*)dst)[2 * j]     = __halves2half2(__float2half(v.x), __float2half(v.y));
    ((__half2*)dst)[2 * j + 1] = __halves2half2(__float2half(v.z), __float2half(v.w));
}

// ---------------- fp16 mma.sync GEMM, merged expert(z<4)+shared(z==4) ----------------
// CTA 128x128, 8 warps (2x4), warp tile 64x32, K-tile 32, 4-stage cp.async, occ 2.
// STAGE 1: A=xf (gathered for z<4), B=W1[e]/sW1 -> gelu -> fp16 store to he/hs
// STAGE 2: A=he (gathered) / hs, B=W2[e]/sW2 -> atomicAdd into out (out pre-zeroed);
//          z==4 multiplies by per-token shared weight.
#define A_TILE_B 10240               // 128 rows * 80B (64B data + 16 pad)
#define B_TILE_B 8704                // 32 rows * 272B (256B data + 16 pad)
#define B_OFF    A_TILE_B
#define STAGE_B  (A_TILE_B + B_TILE_B)   // 18944
#define NSTAGE   4
#define SMEM_GEMM (NSTAGE * STAGE_B)     // 75776

template<int STAGE>
__global__ __launch_bounds__(256, 2)
void mma_gemm(const __half* __restrict__ Ae_g,   // expert A (gathered)
              const __half* __restrict__ As_g,   // shared A (direct)
              const __half* __restrict__ Be_g,   // expert weights base
              const __half* __restrict__ Bs_g,   // shared weights
              const float* __restrict__ biase,
              const float* __restrict__ biass,
              __half* __restrict__ he,           // STAGE1 dest (expert)
              __half* __restrict__ hs,           //              (shared)
              float* __restrict__ outp,          // STAGE2 dest
              int K, int N)
{
    extern __shared__ __align__(16) char smem[];
    const int z = blockIdx.z;
    const bool sp = (z == NEXP);
    int Mtot = TOK;
    const int* bucket = nullptr;
    const __half* Ag = sp ? As_g : Ae_g;
    const __half* Bg = sp ? Bs_g : Be_g + (size_t)z * (size_t)K * N;
    const float* bias = sp ? biass : biase + (size_t)z * N;
    if (!sp) {
        Mtot = g_cnt[z];
        if ((int)(blockIdx.y * 128) >= Mtot) return;
        bucket = g_bucket + z * TOK;
    }
    const int tid = threadIdx.x;
    const int wid = tid >> 5, lane = tid & 31;
    const int mbase = blockIdx.y * 128, nbase = blockIdx.x * 128;
    const uint32_t sb = smem_u32(smem);

    // ---- A loader: rows rA0 (0..63), rA1 (64..127), 16B chunk ck ----
    const int rA0 = tid >> 2, rA1 = 64 + (tid >> 2);
    const int ck  = tid & 3;
    int tok0, tok1; bool v0, v1;
    if (!sp) {
        v0 = (mbase + rA0) < Mtot; tok0 = v0 ? bucket[mbase + rA0] : 0;
        v1 = (mbase + rA1) < Mtot; tok1 = v1 ? bucket[mbase + rA1] : 0;
    } else {
        v0 = v1 = true; tok0 = mbase + rA0; tok1 = mbase + rA1;
    }
    const __half* aP0 = Ag + (size_t)tok0 * K + ck * 8;
    const __half* aP1 = Ag + (size_t)tok1 * K + ck * 8;
    const uint32_t oA0 = (uint32_t)rA0 * 80 + ck * 16;
    const uint32_t oA1 = (uint32_t)rA1 * 80 + ck * 16;

    // ---- B loader: 32 k-rows x 256B ----
    const int rB = tid >> 3, cB = tid & 7;
    const __half* bp = Bg + (size_t)rB * N + nbase + cB * 8;
    const uint32_t oB = (uint32_t)rB * 272 + cB * 16;

    #define LOAD_STAGE(stg, koff) do {                                       \
        uint32_t b_ = sb + (uint32_t)(stg) * STAGE_B;                        \
        cp16(b_ + oA0, aP0 + (koff), v0);                                    \
        cp16(b_ + oA1, aP1 + (koff), v1);                                    \
        cp16(b_ + B_OFF + oB,       bp + (size_t)(koff) * N, true);          \
        cp16(b_ + B_OFF + oB + 128, bp + (size_t)(koff) * N + 64, true);     \
    } while (0)

    const int KT = K / 32;
    LOAD_STAGE(0, 0);  CP_COMMIT();
    LOAD_STAGE(1, 32); CP_COMMIT();
    LOAD_STAGE(2, 64); CP_COMMIT();

    // ---- compute mapping ----
    const int warpM = (wid & 1) * 64;
    const int warpN = (wid >> 1) * 32;
    float acc[4][4][4];
    #pragma unroll
    for (int mi = 0; mi < 4; mi++)
        #pragma unroll
        for (int ni = 0; ni < 4; ni++)
            #pragma unroll
            for (int q = 0; q < 4; q++) acc[mi][ni][q] = 0.f;

    const uint32_t aRowOff = (uint32_t)(warpM + (lane & 15)) * 80 + (lane >> 4) * 16;
    const uint32_t bOffBase = (uint32_t)((lane & 7) + ((lane >> 3) & 1) * 8) * 272
                              + (uint32_t)warpN * 2 + (uint32_t)(lane >> 4) * 16;

    int s_c = 0;
    for (int kt = 0; kt < KT; kt++) {
        CP_WAIT2();
        __syncthreads();
        if (kt + 3 < KT) {
            int s_l = s_c + 3; if (s_l >= NSTAGE) s_l -= NSTAGE;
            LOAD_STAGE(s_l, (kt + 3) * 32);
        }
        CP_COMMIT();

        uint32_t base = sb + (uint32_t)s_c * STAGE_B;
        #pragma unroll
        for (int ks = 0; ks < 2; ks++) {
            uint32_t bF[4][2];
            #pragma unroll
            for (int p = 0; p < 2; p++) {
                uint32_t r0, r1, r2, r3;
                ldsm4t(r0, r1, r2, r3,
                       base + B_OFF + bOffBase + (uint32_t)ks * (16 * 272) + (uint32_t)p * 32);
                bF[2 * p][0] = r0; bF[2 * p][1] = r1;
                bF[2 * p + 1][0] = r2; bF[2 * p + 1][1] = r3;
            }
            uint32_t aF[4][4];
            #pragma unroll
            for (int mi = 0; mi < 4; mi++) {
                uint32_t ad = base + aRowOff + (uint32_t)mi * (16 * 80) + ks * 32;
                ldsm4(aF[mi][0], aF[mi][1], aF[mi][2], aF[mi][3], ad);
            }
            #pragma unroll
            for (int mi = 0; mi < 4; mi++)
                #pragma unroll
                for (int ni = 0; ni < 4; ni++)
                    mma16816(acc[mi][ni], aF[mi], bF[ni]);
        }
        s_c = (s_c + 1 == NSTAGE) ? 0 : s_c + 1;
    }

    // ---- epilogue ----
    float bb[4][2];
    #pragma unroll
    for (int ni = 0; ni < 4; ni++) {
        int n = nbase + warpN + ni * 8 + (lane & 3) * 2;
        bb[ni][0] = bias[n]; bb[ni][1] = bias[n + 1];
    }
    __half* hdst = sp ? hs : he;

    #pragma unroll
    for (int mi = 0; mi < 4; mi++) {
        #pragma unroll
        for (int h = 0; h < 2; h++) {
            int pos = mbase + warpM + mi * 16 + (lane >> 2) + h * 8;
            int et; bool ev;
            if (!sp) { ev = pos < Mtot; et = ev ? bucket[pos] : 0; }
            else { ev = true; et = pos; }
            if (!ev) continue;
            float swv = (STAGE == 2 && sp) ? g_sw[et] : 1.f;
            #pragma unroll
            for (int ni = 0; ni < 4; ni++) {
                int n = nbase + warpN + ni * 8 + (lane & 3) * 2;
                float u0 = acc[mi][ni][2 * h]     + bb[ni][0];
                float u1 = acc[mi][ni][2 * h + 1] + bb[ni][1];
                if (STAGE == 1) {
                    u0 = 0.5f * u0 * (1.f + erff(u0 * 0.70710678118f));
                    u1 = 0.5f * u1 * (1.f + erff(u1 * 0.70710678118f));
                    *(__half2*)(hdst + (size_t)et * HDIM + n) =
                        __halves2half2(__float2half(u0), __float2half(u1));
                } else {
                    float* dst = outp + (size_t)et * DDIM + n;
                    atomicAdd(dst,     swv * u0);
                    atomicAdd(dst + 1, swv * u1);
                }
            }
        }
    }
    #undef LOAD_STAGE
}

// ---------------- launch ----------------
extern "C" void kernel_launch(void* const* d_in, const int* in_sizes, int n_in,
                              void* d_out, int out_size) {
    const float* x   = (const float*)d_in[0];
    const float* gW  = (const float*)d_in[1];
    const float* gb  = (const float*)d_in[2];
    const float* W1  = (const float*)d_in[3];
    const float* b1  = (const float*)d_in[4];
    const float* W2  = (const float*)d_in[5];
    const float* b2  = (const float*)d_in[6];
    const float* sW1 = (const float*)d_in[7];
    const float* sb1 = (const float*)d_in[8];
    const float* sW2 = (const float*)d_in[9];
    const float* sb2 = (const float*)d_in[10];
    const float* shw = (const float*)d_in[11];

    float* out  = (float*)d_out;
    float* auxp = out + (size_t)TOK * DDIM;
    float* gate = auxp + 1;

    cudaFuncSetAttribute(mma_gemm<1>, cudaFuncAttributeMaxDynamicSharedMemorySize, SMEM_GEMM);
    cudaFuncSetAttribute(mma_gemm<2>, cudaFuncAttributeMaxDynamicSharedMemorySize, SMEM_GEMM);

    __half *xf, *w1, *w2, *s1, *s2, *he, *hs;
    cudaGetSymbolAddress((void**)&xf, g_xf);
    cudaGetSymbolAddress((void**)&w1, g_w1); cudaGetSymbolAddress((void**)&w2, g_w2);
    cudaGetSymbolAddress((void**)&s1, g_s1); cudaGetSymbolAddress((void**)&s2, g_s2);
    cudaGetSymbolAddress((void**)&he, g_he); cudaGetSymbolAddress((void**)&hs, g_hs);

    zero_kernel<<<1, 32>>>();
    router_kernel<<<TOK / 8, 256>>>(x, gW, gb, shw, gate);
    aux_kernel<<<1, 1024>>>(gate, auxp);
    convert_all_kernel<<<(N4_TOTAL + 255) / 256, 256>>>(
        x, W1, W2, sW1, sW2, xf, w1, w2, s1, s2);
    cudaMemsetAsync(out, 0, (size_t)TOK * DDIM * sizeof(float));

    // stage 1: expert (z 0..3) + shared (z 4) -> he / hs
    mma_gemm<1><<<dim3(HDIM / 128, TOK / 128, NEXP + 1), 256, SMEM_GEMM>>>(
        xf, xf, w1, s1, b1, sb1, he, hs, nullptr, DDIM, HDIM);
    // stage 2: expert + shared -> atomicAdd into out
    mma_gemm<2><<<dim3(DDIM / 128, TOK / 128, NEXP + 1), 256, SMEM_GEMM>>>(
        he, hs, w2, s2, b2, sb2, nullptr, nullptr, out, HDIM, DDIM);
}